// round 10
// baseline (speedup 1.0000x reference)
#include <cuda_runtime.h>
#include <math.h>
#include <stdint.h>

#define S_    4096
#define D_    768
#define H_    12
#define HD_   64
#define NCLS_ 64
#define FF_   3072
#define WIN_  256
#define LAYERS_ 2

typedef unsigned long long u64;

// ---------------- scratch (static device globals; no allocation) ----------------
__device__ float g_h  [S_*D_];
__device__ float g_q  [S_*D_];
__device__ float g_k  [S_*D_];
__device__ float g_v  [S_*D_];
__device__ float g_kg [S_*D_];
__device__ float g_vg [S_*D_];
__device__ float g_out[S_*D_];
__device__ float g_tmp[S_*D_];
__device__ float g_ff [S_*FF_];
__device__ float g_hg [NCLS_*D_];
__device__ float g_qg [NCLS_*D_];
__device__ int   g_glb[S_];

// ---------------- packed f32x2 helpers ----------------
static __device__ __forceinline__ u64 dup_f32x2(float x) {
    u64 r; asm("mov.b64 %0, {%1, %1};" : "=l"(r) : "f"(x)); return r;
}
static __device__ __forceinline__ void ffma2(u64& c, u64 a, u64 b) {
    asm("fma.rn.f32x2 %0, %1, %2, %0;" : "+l"(c) : "l"(a), "l"(b));
}
static __device__ __forceinline__ void unpack2(float& lo, float& hi, u64 v) {
    asm("mov.b64 {%0, %1}, %2;" : "=f"(lo), "=f"(hi) : "l"(v));
}

// ---------------- batched SGEMM: C[z] = A @ B[z] + bias[z], optional gelu ----------------
// 128x128 tile, BK=16, double-buffered, packed-f32x2 inner loop.
#define BK_   16
#define SAS_  132
#define NBAT_ 5
struct GemmArgs {
    const float* B[NBAT_];
    const float* bias[NBAT_];
    float*       C[NBAT_];
};
__global__ __launch_bounds__(256) void sgemm2_kernel(
    const float* __restrict__ A, GemmArgs args,
    int M, int N, int K, int act)
{
    const float* __restrict__ Bg   = args.B[blockIdx.z];
    const float* __restrict__ bias = args.bias[blockIdx.z];
    float* __restrict__ C          = args.C[blockIdx.z];

    __shared__ float As[2][BK_ * SAS_];
    __shared__ float Bs[2][BK_ * 128];
    const int tid = threadIdx.x;
    const int tx = tid & 15;
    const int ty = tid >> 4;
    const int blockRow = blockIdx.y * 128;
    const int blockCol = blockIdx.x * 128;
    const int aRow = tid >> 1;
    const int aCol = (tid & 1) * 8;
    const int bRow = tid >> 4;
    const int bCol = (tid & 15) * 8;

    u64 acc2[8][4];
#pragma unroll
    for (int i = 0; i < 8; i++)
#pragma unroll
        for (int jp = 0; jp < 4; jp++) acc2[i][jp] = 0ull;

    const float* Ap = A + (size_t)(blockRow + aRow) * K + aCol;
    const float* Bp = Bg + (size_t)bRow * N + blockCol + bCol;
    const bool aOk = (blockRow + aRow) < M;

    float4 pa0, pa1, pb0, pb1;
    pa0 = make_float4(0.f, 0.f, 0.f, 0.f); pa1 = pa0;
    if (aOk) { pa0 = *reinterpret_cast<const float4*>(Ap);
               pa1 = *reinterpret_cast<const float4*>(Ap + 4); }
    pb0 = *reinterpret_cast<const float4*>(Bp);
    pb1 = *reinterpret_cast<const float4*>(Bp + 4);
    {
        float* as = As[0];
        as[(aCol + 0) * SAS_ + aRow] = pa0.x;
        as[(aCol + 1) * SAS_ + aRow] = pa0.y;
        as[(aCol + 2) * SAS_ + aRow] = pa0.z;
        as[(aCol + 3) * SAS_ + aRow] = pa0.w;
        as[(aCol + 4) * SAS_ + aRow] = pa1.x;
        as[(aCol + 5) * SAS_ + aRow] = pa1.y;
        as[(aCol + 6) * SAS_ + aRow] = pa1.z;
        as[(aCol + 7) * SAS_ + aRow] = pa1.w;
        *reinterpret_cast<float4*>(Bs[0] + bRow * 128 + bCol) = pb0;
        *reinterpret_cast<float4*>(Bs[0] + bRow * 128 + bCol + 4) = pb1;
    }
    __syncthreads();

    int s = 0;
    for (int k0 = BK_; k0 < K; k0 += BK_) {
        pa0 = make_float4(0.f, 0.f, 0.f, 0.f); pa1 = pa0;
        if (aOk) { pa0 = *reinterpret_cast<const float4*>(Ap + k0);
                   pa1 = *reinterpret_cast<const float4*>(Ap + k0 + 4); }
        pb0 = *reinterpret_cast<const float4*>(Bp + (size_t)k0 * N);
        pb1 = *reinterpret_cast<const float4*>(Bp + (size_t)k0 * N + 4);

        const float* as = As[s];
        const float* bs = Bs[s];
#pragma unroll
        for (int kk = 0; kk < BK_; kk++) {
            float a[8];
            u64 b[4];
            *reinterpret_cast<float4*>(a)     = *reinterpret_cast<const float4*>(as + kk * SAS_ + ty * 8);
            *reinterpret_cast<float4*>(a + 4) = *reinterpret_cast<const float4*>(as + kk * SAS_ + ty * 8 + 4);
            *reinterpret_cast<ulonglong2*>(b)     = *reinterpret_cast<const ulonglong2*>(bs + kk * 128 + tx * 8);
            *reinterpret_cast<ulonglong2*>(b + 2) = *reinterpret_cast<const ulonglong2*>(bs + kk * 128 + tx * 8 + 4);
#pragma unroll
            for (int i = 0; i < 8; i++) {
                const u64 ad = dup_f32x2(a[i]);
#pragma unroll
                for (int jp = 0; jp < 4; jp++) ffma2(acc2[i][jp], ad, b[jp]);
            }
        }

        float* asn = As[s ^ 1];
        asn[(aCol + 0) * SAS_ + aRow] = pa0.x;
        asn[(aCol + 1) * SAS_ + aRow] = pa0.y;
        asn[(aCol + 2) * SAS_ + aRow] = pa0.z;
        asn[(aCol + 3) * SAS_ + aRow] = pa0.w;
        asn[(aCol + 4) * SAS_ + aRow] = pa1.x;
        asn[(aCol + 5) * SAS_ + aRow] = pa1.y;
        asn[(aCol + 6) * SAS_ + aRow] = pa1.z;
        asn[(aCol + 7) * SAS_ + aRow] = pa1.w;
        *reinterpret_cast<float4*>(Bs[s ^ 1] + bRow * 128 + bCol) = pb0;
        *reinterpret_cast<float4*>(Bs[s ^ 1] + bRow * 128 + bCol + 4) = pb1;
        __syncthreads();
        s ^= 1;
    }

    {
        const float* as = As[s];
        const float* bs = Bs[s];
#pragma unroll
        for (int kk = 0; kk < BK_; kk++) {
            float a[8];
            u64 b[4];
            *reinterpret_cast<float4*>(a)     = *reinterpret_cast<const float4*>(as + kk * SAS_ + ty * 8);
            *reinterpret_cast<float4*>(a + 4) = *reinterpret_cast<const float4*>(as + kk * SAS_ + ty * 8 + 4);
            *reinterpret_cast<ulonglong2*>(b)     = *reinterpret_cast<const ulonglong2*>(bs + kk * 128 + tx * 8);
            *reinterpret_cast<ulonglong2*>(b + 2) = *reinterpret_cast<const ulonglong2*>(bs + kk * 128 + tx * 8 + 4);
#pragma unroll
            for (int i = 0; i < 8; i++) {
                const u64 ad = dup_f32x2(a[i]);
#pragma unroll
                for (int jp = 0; jp < 4; jp++) ffma2(acc2[i][jp], ad, b[jp]);
            }
        }
    }

#pragma unroll
    for (int i = 0; i < 8; i++) {
        int r = blockRow + ty * 8 + i;
        if (r >= M) continue;
#pragma unroll
        for (int jp = 0; jp < 4; jp++) {
            int c = blockCol + tx * 8 + jp * 2;
            float v0, v1;
            unpack2(v0, v1, acc2[i][jp]);
            v0 += bias[c];
            v1 += bias[c + 1];
            if (act == 1) {
                float u0 = 0.7978845608028654f * (v0 + 0.044715f * v0 * v0 * v0);
                float t0 = 1.f - 2.f / (__expf(2.f * u0) + 1.f);
                v0 = 0.5f * v0 * (1.f + t0);
                float u1 = 0.7978845608028654f * (v1 + 0.044715f * v1 * v1 * v1);
                float t1 = 1.f - 2.f / (__expf(2.f * u1) + 1.f);
                v1 = 0.5f * v1 * (1.f + t1);
            }
            *reinterpret_cast<float2*>(C + (size_t)r * N + c) = make_float2(v0, v1);
        }
    }
}

// ---------------- embedding + layernorm ----------------
__global__ __launch_bounds__(256) void embed_ln_kernel(
    const int* __restrict__ x, const int* __restrict__ segs,
    const float* __restrict__ we, const float* __restrict__ pe, const float* __restrict__ te,
    const float* __restrict__ lns, const float* __restrict__ lnb,
    float* __restrict__ hout)
{
    int s = blockIdx.x;
    int tid = threadIdx.x;
    __shared__ float buf[D_];
    __shared__ float red[256];
    int tok = x[s], seg = segs[s];
    float lsum = 0.f;
    for (int d = tid; d < D_; d += 256) {
        float v = we[(size_t)tok * D_ + d] + pe[(size_t)s * D_ + d] + te[(size_t)seg * D_ + d];
        buf[d] = v;
        lsum += v;
    }
    red[tid] = lsum; __syncthreads();
    for (int o = 128; o > 0; o >>= 1) { if (tid < o) red[tid] += red[tid + o]; __syncthreads(); }
    float mean = red[0] / D_;
    __syncthreads();
    float vsum = 0.f;
    for (int d = tid; d < D_; d += 256) { float t = buf[d] - mean; vsum += t * t; }
    red[tid] = vsum; __syncthreads();
    for (int o = 128; o > 0; o >>= 1) { if (tid < o) red[tid] += red[tid + o]; __syncthreads(); }
    float rstd = rsqrtf(red[0] / D_ + 1e-5f);
    for (int d = tid; d < D_; d += 256)
        hout[(size_t)s * D_ + d] = (buf[d] - mean) * rstd * lns[d] + lnb[d];
}

// ---------------- residual add + layernorm (in-place into h) ----------------
__global__ __launch_bounds__(256) void add_ln_kernel(
    float* __restrict__ h, const float* __restrict__ t,
    const float* __restrict__ lns, const float* __restrict__ lnb)
{
    int s = blockIdx.x;
    int tid = threadIdx.x;
    __shared__ float buf[D_];
    __shared__ float red[256];
    float lsum = 0.f;
    for (int d = tid; d < D_; d += 256) {
        float v = h[(size_t)s * D_ + d] + t[(size_t)s * D_ + d];
        buf[d] = v;
        lsum += v;
    }
    red[tid] = lsum; __syncthreads();
    for (int o = 128; o > 0; o >>= 1) { if (tid < o) red[tid] += red[tid + o]; __syncthreads(); }
    float mean = red[0] / D_;
    __syncthreads();
    float vsum = 0.f;
    for (int d = tid; d < D_; d += 256) { float x = buf[d] - mean; vsum += x * x; }
    red[tid] = vsum; __syncthreads();
    for (int o = 128; o > 0; o >>= 1) { if (tid < o) red[tid] += red[tid + o]; __syncthreads(); }
    float rstd = rsqrtf(red[0] / D_ + 1e-5f);
    for (int d = tid; d < D_; d += 256)
        h[(size_t)s * D_ + d] = (buf[d] - mean) * rstd * lns[d] + lnb[d];
}

// ---------------- global flags ----------------
__global__ void zero_flags_kernel(int* f)
{
    int i = blockIdx.x * 256 + threadIdx.x;
    if (i < S_) f[i] = 0;
}
__global__ void set_flags_kernel(const int* __restrict__ clss, int* f)
{
    if (threadIdx.x < NCLS_) f[clss[threadIdx.x]] = 1;
}
__global__ __launch_bounds__(256) void gather_rows_kernel(
    const float* __restrict__ h, const int* __restrict__ clss, float* __restrict__ hg)
{
    int c = blockIdx.x;
    int gp = clss[c];
    for (int d = threadIdx.x; d < D_; d += 256)
        hg[(size_t)c * D_ + d] = h[(size_t)gp * D_ + d];
}

// ================ tiled flash-style band + global-key attention ================
#define BKEY_ 128
#define NCH_  5
#define KS_   132
#define VS_   68
#define PS_   72
#define OF_Q  0
#define OF_K  4096
#define OF_V  (OF_K + 64*KS_)
#define OF_P  (OF_V + BKEY_*VS_)
#define OF_KV (OF_P + BKEY_*PS_)
#define OF_SC (OF_KV + BKEY_)
#define OF_SI (OF_SC + 64)
#define BAND_SMEM ((OF_SI + 64) * 4)

__global__ __launch_bounds__(256) void band_attn_tiled_kernel(
    const float* __restrict__ q, const float* __restrict__ k, const float* __restrict__ v,
    const int* __restrict__ clss, const int* __restrict__ mask_src, const int* __restrict__ glb,
    float* __restrict__ out)
{
    extern __shared__ float sm[];
    float* Qsd = sm + OF_Q;
    float* Ksd = sm + OF_K;
    float* Vs  = sm + OF_V;
    float* Pkq = sm + OF_P;
    int*   kvl = (int*)(sm + OF_KV);
    float* ssc = sm + OF_SC;
    float* sin_ = sm + OF_SI;

    const int c = blockIdx.x, hh = blockIdx.y;
    const int s0 = c * 64;
    const int t = threadIdx.x;
    const int w = t >> 5, lane = t & 31;

    for (int idx = t; idx < 64 * 16; idx += 256) {
        const int r = idx >> 4, seg = (idx & 15) * 4;
        const float4 qv = *reinterpret_cast<const float4*>(
            q + ((size_t)(s0 + r) * H_ + hh) * HD_ + seg);
        Qsd[(seg + 0) * 64 + r] = qv.x * 0.125f;
        Qsd[(seg + 1) * 64 + r] = qv.y * 0.125f;
        Qsd[(seg + 2) * 64 + r] = qv.z * 0.125f;
        Qsd[(seg + 3) * 64 + r] = qv.w * 0.125f;
    }

    float mstate = -1e30f, ssum = 0.f;
    float O[8][2];
#pragma unroll
    for (int j = 0; j < 8; j++) { O[j][0] = 0.f; O[j][1] = 0.f; }

    const int tq = t >> 4, tk = t & 15;
    const int r0 = tq * 4, kk0 = tk * 8;

    for (int ch = 0; ch < NCH_; ch++) {
        for (int idx = t; idx < BKEY_ * 16; idx += 256) {
            const int kr = idx >> 4, seg = (idx & 15) * 4;
            const int gi = ch * BKEY_ + kr;
            int p; int val;
            if (gi < NCLS_) {
                p = clss[gi];
                val = (mask_src[p] > 0);
            } else {
                p = s0 + gi - 320;
                val = (p >= 0 && p < S_);
                if (val) val = (mask_src[p] > 0) && (glb[p] == 0);
                if (!val) p = 0;
            }
            if ((idx & 15) == 0) kvl[kr] = val;
            const float4 kv = *reinterpret_cast<const float4*>(
                k + ((size_t)p * H_ + hh) * HD_ + seg);
            Ksd[(seg + 0) * KS_ + kr] = kv.x;
            Ksd[(seg + 1) * KS_ + kr] = kv.y;
            Ksd[(seg + 2) * KS_ + kr] = kv.z;
            Ksd[(seg + 3) * KS_ + kr] = kv.w;
            *reinterpret_cast<float4*>(Vs + kr * VS_ + seg) =
                *reinterpret_cast<const float4*>(v + ((size_t)p * H_ + hh) * HD_ + seg);
        }
        __syncthreads();

        float sc[4][8];
#pragma unroll
        for (int j = 0; j < 4; j++)
#pragma unroll
            for (int i = 0; i < 8; i++) sc[j][i] = 0.f;
#pragma unroll 8
        for (int d = 0; d < 64; d++) {
            const float4 a = *reinterpret_cast<const float4*>(Qsd + d * 64 + r0);
            const float4 b0 = *reinterpret_cast<const float4*>(Ksd + d * KS_ + kk0);
            const float4 b1 = *reinterpret_cast<const float4*>(Ksd + d * KS_ + kk0 + 4);
            const float aa[4] = {a.x, a.y, a.z, a.w};
            const float bb[8] = {b0.x, b0.y, b0.z, b0.w, b1.x, b1.y, b1.z, b1.w};
#pragma unroll
            for (int j = 0; j < 4; j++)
#pragma unroll
                for (int i = 0; i < 8; i++) sc[j][i] = fmaf(aa[j], bb[i], sc[j][i]);
        }
#pragma unroll
        for (int i = 0; i < 8; i++) {
            const int gi = ch * BKEY_ + kk0 + i;
            const int kvalid = kvl[kk0 + i];
#pragma unroll
            for (int j = 0; j < 4; j++) {
                const int r = r0 + j;
                const bool ok = kvalid &&
                    (gi < NCLS_ || (r >= gi - 576 && r <= gi - 64));
                Pkq[(kk0 + i) * PS_ + r] = ok ? sc[j][i] : -1e30f;
            }
        }
        __syncthreads();

        if (t < 64) {
            float mn = mstate;
            for (int kk = 0; kk < BKEY_; kk++) mn = fmaxf(mn, Pkq[kk * PS_ + t]);
            const float scale = (mn <= -1e29f) ? 1.f : __expf(mstate - mn);
            float ls = 0.f;
            for (int kk = 0; kk < BKEY_; kk++) {
                const float sv = Pkq[kk * PS_ + t];
                const float pv = (sv <= -1e29f) ? 0.f : __expf(sv - mn);
                Pkq[kk * PS_ + t] = pv;
                ls += pv;
            }
            ssum = ssum * scale + ls;
            mstate = mn;
            ssc[t] = scale;
        }
        __syncthreads();

        {
#pragma unroll
            for (int j = 0; j < 8; j++) {
                const float scj = ssc[w * 8 + j];
                O[j][0] *= scj; O[j][1] *= scj;
            }
            for (int kk = 0; kk < BKEY_; kk++) {
                const float4 pa = *reinterpret_cast<const float4*>(Pkq + kk * PS_ + w * 8);
                const float4 pb = *reinterpret_cast<const float4*>(Pkq + kk * PS_ + w * 8 + 4);
                const float v0 = Vs[kk * VS_ + lane];
                const float v1 = Vs[kk * VS_ + lane + 32];
                O[0][0] = fmaf(pa.x, v0, O[0][0]); O[0][1] = fmaf(pa.x, v1, O[0][1]);
                O[1][0] = fmaf(pa.y, v0, O[1][0]); O[1][1] = fmaf(pa.y, v1, O[1][1]);
                O[2][0] = fmaf(pa.z, v0, O[2][0]); O[2][1] = fmaf(pa.z, v1, O[2][1]);
                O[3][0] = fmaf(pa.w, v0, O[3][0]); O[3][1] = fmaf(pa.w, v1, O[3][1]);
                O[4][0] = fmaf(pb.x, v0, O[4][0]); O[4][1] = fmaf(pb.x, v1, O[4][1]);
                O[5][0] = fmaf(pb.y, v0, O[5][0]); O[5][1] = fmaf(pb.y, v1, O[5][1]);
                O[6][0] = fmaf(pb.z, v0, O[6][0]); O[6][1] = fmaf(pb.z, v1, O[6][1]);
                O[7][0] = fmaf(pb.w, v0, O[7][0]); O[7][1] = fmaf(pb.w, v1, O[7][1]);
            }
        }
        __syncthreads();
    }

    if (t < 64) sin_[t] = 1.f / ssum;
    __syncthreads();
#pragma unroll
    for (int j = 0; j < 8; j++) {
        const int qr = w * 8 + j;
        const float inv = sin_[qr];
        float* op = out + ((size_t)(s0 + qr) * H_ + hh) * HD_;
        op[lane]      = O[j][0] * inv;
        op[lane + 32] = O[j][1] * inv;
    }
}

// ---------------- global-query full attention: one block per (c, head) ----------------
__global__ __launch_bounds__(256) void glb_attn_kernel(
    const float* __restrict__ qg, const float* __restrict__ kg, const float* __restrict__ vg,
    const int* __restrict__ clss, const int* __restrict__ mask_src,
    float* __restrict__ out)
{
    const int c = blockIdx.x;
    const int h = blockIdx.y;
    __shared__ float qs[HD_];
    __shared__ float sc[S_];
    __shared__ float red[256];
    const int tid = threadIdx.x;
    const int lane = tid & 31;
    const int w = tid >> 5;

    if (tid < HD_) qs[tid] = qg[((size_t)c * H_ + h) * HD_ + tid] * 0.125f;
    __syncthreads();

    for (int p = w; p < S_; p += 8) {
        const float* kp = kg + ((size_t)p * H_ + h) * HD_;
        float sdot = qs[lane] * kp[lane] + qs[lane + 32] * kp[lane + 32];
#pragma unroll
        for (int o = 16; o > 0; o >>= 1) sdot += __shfl_xor_sync(0xffffffffu, sdot, o);
        if (lane == 0) sc[p] = (mask_src[p] > 0) ? sdot : -1e30f;
    }
    __syncthreads();

    float m = -1e30f;
    for (int p = tid; p < S_; p += 256) m = fmaxf(m, sc[p]);
    red[tid] = m; __syncthreads();
    for (int o = 128; o > 0; o >>= 1) { if (tid < o) red[tid] = fmaxf(red[tid], red[tid + o]); __syncthreads(); }
    m = red[0];
    __syncthreads();
    float sum = 0.f;
    for (int p = tid; p < S_; p += 256) { float e = __expf(sc[p] - m); sc[p] = e; sum += e; }
    red[tid] = sum; __syncthreads();
    for (int o = 128; o > 0; o >>= 1) { if (tid < o) red[tid] += red[tid + o]; __syncthreads(); }
    float inv = 1.f / red[0];
    __syncthreads();

    int d = tid & 63, quarter = tid >> 6;
    float acc = 0.f;
    for (int p = quarter; p < S_; p += 4)
        acc += sc[p] * vg[((size_t)p * H_ + h) * HD_ + d];
    red[tid] = acc; __syncthreads();
    if (tid < 64) {
        float o = (red[tid] + red[tid + 64] + red[tid + 128] + red[tid + 192]) * inv;
        int gp = clss[c];
        out[((size_t)gp * H_ + h) * HD_ + tid] = o;
    }
}

// ---------------- driver ----------------
static void run_gemm1(const float* A, const float* B, const float* bias, float* C,
                      int M, int N, int K, int act)
{
    GemmArgs ga;
    for (int i = 0; i < NBAT_; i++) { ga.B[i] = B; ga.bias[i] = bias; ga.C[i] = C; }
    dim3 grid(N / 128, (M + 127) / 128, 1);
    sgemm2_kernel<<<grid, 256>>>(A, ga, M, N, K, act);
}

extern "C" void kernel_launch(void* const* d_in, const int* in_sizes, int n_in,
                              void* d_out, int out_size)
{
    (void)in_sizes; (void)n_in;
    const int*   x        = (const int*)d_in[0];
    const int*   mask_src = (const int*)d_in[1];
    const int*   clss     = (const int*)d_in[2];
    const int*   segs     = (const int*)d_in[3];
    const float* word_emb = (const float*)d_in[4];
    const float* pos_emb  = (const float*)d_in[5];
    const float* type_emb = (const float*)d_in[6];
    const float* ln_e_s   = (const float*)d_in[7];
    const float* ln_e_b   = (const float*)d_in[8];
    const float* Wq  = (const float*)d_in[9];   const float* bq  = (const float*)d_in[10];
    const float* Wk  = (const float*)d_in[11];  const float* bk  = (const float*)d_in[12];
    const float* Wv  = (const float*)d_in[13];  const float* bv  = (const float*)d_in[14];
    const float* Wqg = (const float*)d_in[15];  const float* bqg = (const float*)d_in[16];
    const float* Wkg = (const float*)d_in[17];  const float* bkg = (const float*)d_in[18];
    const float* Wvg = (const float*)d_in[19];  const float* bvg = (const float*)d_in[20];
    const float* Wo  = (const float*)d_in[21];  const float* bo  = (const float*)d_in[22];
    const float* ln1_s = (const float*)d_in[23]; const float* ln1_b = (const float*)d_in[24];
    const float* Wf1 = (const float*)d_in[25];  const float* bf1 = (const float*)d_in[26];
    const float* Wf2 = (const float*)d_in[27];  const float* bf2 = (const float*)d_in[28];
    const float* ln2_s = (const float*)d_in[29]; const float* ln2_b = (const float*)d_in[30];

    float *h, *q, *k, *v, *kg, *vg, *outb, *tmp, *ff, *hg, *qg;
    int* glb;
    cudaGetSymbolAddress((void**)&h,    g_h);
    cudaGetSymbolAddress((void**)&q,    g_q);
    cudaGetSymbolAddress((void**)&k,    g_k);
    cudaGetSymbolAddress((void**)&v,    g_v);
    cudaGetSymbolAddress((void**)&kg,   g_kg);
    cudaGetSymbolAddress((void**)&vg,   g_vg);
    cudaGetSymbolAddress((void**)&outb, g_out);
    cudaGetSymbolAddress((void**)&tmp,  g_tmp);
    cudaGetSymbolAddress((void**)&ff,   g_ff);
    cudaGetSymbolAddress((void**)&hg,   g_hg);
    cudaGetSymbolAddress((void**)&qg,   g_qg);
    cudaGetSymbolAddress((void**)&glb,  g_glb);

    cudaFuncSetAttribute(band_attn_tiled_kernel,
                         cudaFuncAttributeMaxDynamicSharedMemorySize, BAND_SMEM);

    // embedding + LN
    embed_ln_kernel<<<S_, 256>>>(x, segs, word_emb, pos_emb, type_emb, ln_e_s, ln_e_b, h);

    // global flags
    zero_flags_kernel<<<(S_ + 255) / 256, 256>>>(glb);
    set_flags_kernel<<<1, 64>>>(clss, glb);

    const size_t DD = (size_t)D_ * D_;
    for (int l = 0; l < LAYERS_; l++) {
        // Q K V Kg Vg projections: one batched launch (shared A = h)
        {
            GemmArgs ga;
            ga.B[0] = Wq  + l * DD; ga.bias[0] = bq  + l * D_; ga.C[0] = q;
            ga.B[1] = Wk  + l * DD; ga.bias[1] = bk  + l * D_; ga.C[1] = k;
            ga.B[2] = Wv  + l * DD; ga.bias[2] = bv  + l * D_; ga.C[2] = v;
            ga.B[3] = Wkg + l * DD; ga.bias[3] = bkg + l * D_; ga.C[3] = kg;
            ga.B[4] = Wvg + l * DD; ga.bias[4] = bvg + l * D_; ga.C[4] = vg;
            dim3 grid(D_ / 128, S_ / 128, NBAT_);
            sgemm2_kernel<<<grid, 256>>>(h, ga, S_, D_, D_, 0);
        }

        // tiled band + global-key attention (writes all rows of outb)
        band_attn_tiled_kernel<<<dim3(S_ / 64, H_), 256, BAND_SMEM>>>(
            q, k, v, clss, mask_src, glb, outb);

        // global-query path
        gather_rows_kernel<<<NCLS_, 256>>>(h, clss, hg);
        run_gemm1(hg, Wqg + l * DD, bqg + l * D_, qg, NCLS_, D_, D_, 0);
        glb_attn_kernel<<<dim3(NCLS_, H_), 256>>>(qg, kg, vg, clss, mask_src, outb);

        // output projection + residual LN
        run_gemm1(outb, Wo + l * DD, bo + l * D_, tmp, S_, D_, D_, 0);
        add_ln_kernel<<<S_, 256>>>(h, tmp, ln1_s + l * D_, ln1_b + l * D_);

        // feed-forward
        run_gemm1(h,  Wf1 + (size_t)l * D_ * FF_, bf1 + l * FF_, ff,  S_, FF_, D_, 1);
        run_gemm1(ff, Wf2 + (size_t)l * D_ * FF_, bf2 + l * D_,  tmp, S_, D_, FF_, 0);
        add_ln_kernel<<<S_, 256>>>(h, tmp, ln2_s + l * D_, ln2_b + l * D_);
    }

    cudaMemcpyAsync(d_out, h, (size_t)out_size * sizeof(float), cudaMemcpyDeviceToDevice);
}

// round 11
// speedup vs baseline: 1.4608x; 1.4608x over previous
#include <cuda_runtime.h>
#include <math.h>
#include <stdint.h>

#define S_    4096
#define D_    768
#define H_    12
#define HD_   64
#define NCLS_ 64
#define FF_   3072
#define WIN_  256
#define LAYERS_ 2

// ---------------- scratch (static device globals; no allocation) ----------------
__device__ float g_h  [S_*D_];
__device__ float g_q  [S_*D_];
__device__ float g_k  [S_*D_];
__device__ float g_v  [S_*D_];
__device__ float g_kg [S_*D_];
__device__ float g_vg [S_*D_];
__device__ float g_out[S_*D_];
__device__ float g_tmp[S_*D_];
__device__ float g_ff [S_*FF_];
__device__ float g_hg [NCLS_*D_];
__device__ float g_qg [NCLS_*D_];
__device__ int   g_glb[S_];

// ---------------- fp32 SGEMM: C = A(MxK) @ B(KxN) + bias, optional gelu ----------------
// 128x128 tile, BK=16, double-buffered smem + gmem register prefetch +
// register fragment double-buffering inside the compute loop.
#define BK_   16
#define SAS_  132   /* padded A-tile k-row stride (floats) */

#define LOADFRAG_(af, bf, as, bs, kk)                                                        \
    *reinterpret_cast<float4*>(af)       = *reinterpret_cast<const float4*>((as) + (kk) * SAS_ + ty * 8);     \
    *reinterpret_cast<float4*>((af) + 4) = *reinterpret_cast<const float4*>((as) + (kk) * SAS_ + ty * 8 + 4); \
    *reinterpret_cast<float4*>(bf)       = *reinterpret_cast<const float4*>((bs) + (kk) * 128 + tx * 8);      \
    *reinterpret_cast<float4*>((bf) + 4) = *reinterpret_cast<const float4*>((bs) + (kk) * 128 + tx * 8 + 4);

#define FMA88_(af, bf)                                       \
    _Pragma("unroll")                                        \
    for (int i_ = 0; i_ < 8; i_++)                           \
        _Pragma("unroll")                                    \
        for (int j_ = 0; j_ < 8; j_++)                       \
            acc[i_][j_] = fmaf((af)[i_], (bf)[j_], acc[i_][j_]);

__global__ __launch_bounds__(256, 2) void sgemm_kernel(
    const float* __restrict__ A, const float* __restrict__ B,
    const float* __restrict__ bias, float* __restrict__ C,
    int M, int N, int K, int act)
{
    __shared__ float As[2][BK_ * SAS_];
    __shared__ float Bs[2][BK_ * 128];
    const int tid = threadIdx.x;
    const int tx = tid & 15;
    const int ty = tid >> 4;
    const int blockRow = blockIdx.y * 128;
    const int blockCol = blockIdx.x * 128;
    const int aRow = tid >> 1;
    const int aCol = (tid & 1) * 8;
    const int bRow = tid >> 4;
    const int bCol = (tid & 15) * 8;

    float acc[8][8];
#pragma unroll
    for (int i = 0; i < 8; i++)
#pragma unroll
        for (int j = 0; j < 8; j++) acc[i][j] = 0.f;

    const float* Ap = A + (size_t)(blockRow + aRow) * K + aCol;
    const float* Bp = B + (size_t)bRow * N + blockCol + bCol;
    const bool aOk = (blockRow + aRow) < M;

    float4 pa0, pa1, pb0, pb1;
    // ---- preload tile 0 ----
    pa0 = make_float4(0.f, 0.f, 0.f, 0.f); pa1 = pa0;
    if (aOk) { pa0 = *reinterpret_cast<const float4*>(Ap);
               pa1 = *reinterpret_cast<const float4*>(Ap + 4); }
    pb0 = *reinterpret_cast<const float4*>(Bp);
    pb1 = *reinterpret_cast<const float4*>(Bp + 4);
    {
        float* as = As[0];
        as[(aCol + 0) * SAS_ + aRow] = pa0.x;
        as[(aCol + 1) * SAS_ + aRow] = pa0.y;
        as[(aCol + 2) * SAS_ + aRow] = pa0.z;
        as[(aCol + 3) * SAS_ + aRow] = pa0.w;
        as[(aCol + 4) * SAS_ + aRow] = pa1.x;
        as[(aCol + 5) * SAS_ + aRow] = pa1.y;
        as[(aCol + 6) * SAS_ + aRow] = pa1.z;
        as[(aCol + 7) * SAS_ + aRow] = pa1.w;
        *reinterpret_cast<float4*>(Bs[0] + bRow * 128 + bCol) = pb0;
        *reinterpret_cast<float4*>(Bs[0] + bRow * 128 + bCol + 4) = pb1;
    }
    __syncthreads();

    int s = 0;
    for (int k0 = BK_; k0 < K; k0 += BK_) {
        // prefetch next gmem tile into registers
        pa0 = make_float4(0.f, 0.f, 0.f, 0.f); pa1 = pa0;
        if (aOk) { pa0 = *reinterpret_cast<const float4*>(Ap + k0);
                   pa1 = *reinterpret_cast<const float4*>(Ap + k0 + 4); }
        pb0 = *reinterpret_cast<const float4*>(Bp + (size_t)k0 * N);
        pb1 = *reinterpret_cast<const float4*>(Bp + (size_t)k0 * N + 4);

        // compute current tile with fragment double-buffering
        {
            const float* as = As[s];
            const float* bs = Bs[s];
            float af[2][8], bf[2][8];
            LOADFRAG_(af[0], bf[0], as, bs, 0);
#pragma unroll
            for (int kk = 0; kk < BK_; kk++) {
                const int cur = kk & 1;
                if (kk + 1 < BK_) {
                    LOADFRAG_(af[cur ^ 1], bf[cur ^ 1], as, bs, kk + 1);
                }
                FMA88_(af[cur], bf[cur]);
            }
        }

        // store prefetched tile into the other buffer
        float* asn = As[s ^ 1];
        asn[(aCol + 0) * SAS_ + aRow] = pa0.x;
        asn[(aCol + 1) * SAS_ + aRow] = pa0.y;
        asn[(aCol + 2) * SAS_ + aRow] = pa0.z;
        asn[(aCol + 3) * SAS_ + aRow] = pa0.w;
        asn[(aCol + 4) * SAS_ + aRow] = pa1.x;
        asn[(aCol + 5) * SAS_ + aRow] = pa1.y;
        asn[(aCol + 6) * SAS_ + aRow] = pa1.z;
        asn[(aCol + 7) * SAS_ + aRow] = pa1.w;
        *reinterpret_cast<float4*>(Bs[s ^ 1] + bRow * 128 + bCol) = pb0;
        *reinterpret_cast<float4*>(Bs[s ^ 1] + bRow * 128 + bCol + 4) = pb1;
        __syncthreads();
        s ^= 1;
    }

    // last tile
    {
        const float* as = As[s];
        const float* bs = Bs[s];
        float af[2][8], bf[2][8];
        LOADFRAG_(af[0], bf[0], as, bs, 0);
#pragma unroll
        for (int kk = 0; kk < BK_; kk++) {
            const int cur = kk & 1;
            if (kk + 1 < BK_) {
                LOADFRAG_(af[cur ^ 1], bf[cur ^ 1], as, bs, kk + 1);
            }
            FMA88_(af[cur], bf[cur]);
        }
    }

#pragma unroll
    for (int i = 0; i < 8; i++) {
        int r = blockRow + ty * 8 + i;
        if (r >= M) continue;
#pragma unroll
        for (int j = 0; j < 8; j++) {
            int c = blockCol + tx * 8 + j;
            float val = acc[i][j] + bias[c];
            if (act == 1) {
                float u = 0.7978845608028654f * (val + 0.044715f * val * val * val);
                float t = 1.f - 2.f / (__expf(2.f * u) + 1.f);
                val = 0.5f * val * (1.f + t);
            }
            C[(size_t)r * N + c] = val;
        }
    }
}

// ---------------- embedding + layernorm ----------------
__global__ __launch_bounds__(256) void embed_ln_kernel(
    const int* __restrict__ x, const int* __restrict__ segs,
    const float* __restrict__ we, const float* __restrict__ pe, const float* __restrict__ te,
    const float* __restrict__ lns, const float* __restrict__ lnb,
    float* __restrict__ hout)
{
    int s = blockIdx.x;
    int tid = threadIdx.x;
    __shared__ float buf[D_];
    __shared__ float red[256];
    int tok = x[s], seg = segs[s];
    float lsum = 0.f;
    for (int d = tid; d < D_; d += 256) {
        float v = we[(size_t)tok * D_ + d] + pe[(size_t)s * D_ + d] + te[(size_t)seg * D_ + d];
        buf[d] = v;
        lsum += v;
    }
    red[tid] = lsum; __syncthreads();
    for (int o = 128; o > 0; o >>= 1) { if (tid < o) red[tid] += red[tid + o]; __syncthreads(); }
    float mean = red[0] / D_;
    __syncthreads();
    float vsum = 0.f;
    for (int d = tid; d < D_; d += 256) { float t = buf[d] - mean; vsum += t * t; }
    red[tid] = vsum; __syncthreads();
    for (int o = 128; o > 0; o >>= 1) { if (tid < o) red[tid] += red[tid + o]; __syncthreads(); }
    float rstd = rsqrtf(red[0] / D_ + 1e-5f);
    for (int d = tid; d < D_; d += 256)
        hout[(size_t)s * D_ + d] = (buf[d] - mean) * rstd * lns[d] + lnb[d];
}

// ---------------- residual add + layernorm (in-place into h) ----------------
__global__ __launch_bounds__(256) void add_ln_kernel(
    float* __restrict__ h, const float* __restrict__ t,
    const float* __restrict__ lns, const float* __restrict__ lnb)
{
    int s = blockIdx.x;
    int tid = threadIdx.x;
    __shared__ float buf[D_];
    __shared__ float red[256];
    float lsum = 0.f;
    for (int d = tid; d < D_; d += 256) {
        float v = h[(size_t)s * D_ + d] + t[(size_t)s * D_ + d];
        buf[d] = v;
        lsum += v;
    }
    red[tid] = lsum; __syncthreads();
    for (int o = 128; o > 0; o >>= 1) { if (tid < o) red[tid] += red[tid + o]; __syncthreads(); }
    float mean = red[0] / D_;
    __syncthreads();
    float vsum = 0.f;
    for (int d = tid; d < D_; d += 256) { float x = buf[d] - mean; vsum += x * x; }
    red[tid] = vsum; __syncthreads();
    for (int o = 128; o > 0; o >>= 1) { if (tid < o) red[tid] += red[tid + o]; __syncthreads(); }
    float rstd = rsqrtf(red[0] / D_ + 1e-5f);
    for (int d = tid; d < D_; d += 256)
        h[(size_t)s * D_ + d] = (buf[d] - mean) * rstd * lns[d] + lnb[d];
}

// ---------------- global flags ----------------
__global__ void zero_flags_kernel(int* f)
{
    int i = blockIdx.x * 256 + threadIdx.x;
    if (i < S_) f[i] = 0;
}
__global__ void set_flags_kernel(const int* __restrict__ clss, int* f)
{
    if (threadIdx.x < NCLS_) f[clss[threadIdx.x]] = 1;
}
__global__ __launch_bounds__(256) void gather_rows_kernel(
    const float* __restrict__ h, const int* __restrict__ clss, float* __restrict__ hg)
{
    int c = blockIdx.x;
    int gp = clss[c];
    for (int d = threadIdx.x; d < D_; d += 256)
        hg[(size_t)c * D_ + d] = h[(size_t)gp * D_ + d];
}

// ================ tiled flash-style band + global-key attention ================
#define BKEY_ 128
#define NCH_  5
#define KS_   132
#define VS_   68
#define PS_   72
#define OF_Q  0
#define OF_K  4096
#define OF_V  (OF_K + 64*KS_)
#define OF_P  (OF_V + BKEY_*VS_)
#define OF_KV (OF_P + BKEY_*PS_)
#define OF_SC (OF_KV + BKEY_)
#define OF_SI (OF_SC + 64)
#define BAND_SMEM ((OF_SI + 64) * 4)

__global__ __launch_bounds__(256) void band_attn_tiled_kernel(
    const float* __restrict__ q, const float* __restrict__ k, const float* __restrict__ v,
    const int* __restrict__ clss, const int* __restrict__ mask_src, const int* __restrict__ glb,
    float* __restrict__ out)
{
    extern __shared__ float sm[];
    float* Qsd = sm + OF_Q;
    float* Ksd = sm + OF_K;
    float* Vs  = sm + OF_V;
    float* Pkq = sm + OF_P;
    int*   kvl = (int*)(sm + OF_KV);
    float* ssc = sm + OF_SC;
    float* sin_ = sm + OF_SI;

    const int c = blockIdx.x, hh = blockIdx.y;
    const int s0 = c * 64;
    const int t = threadIdx.x;
    const int w = t >> 5, lane = t & 31;

    for (int idx = t; idx < 64 * 16; idx += 256) {
        const int r = idx >> 4, seg = (idx & 15) * 4;
        const float4 qv = *reinterpret_cast<const float4*>(
            q + ((size_t)(s0 + r) * H_ + hh) * HD_ + seg);
        Qsd[(seg + 0) * 64 + r] = qv.x * 0.125f;
        Qsd[(seg + 1) * 64 + r] = qv.y * 0.125f;
        Qsd[(seg + 2) * 64 + r] = qv.z * 0.125f;
        Qsd[(seg + 3) * 64 + r] = qv.w * 0.125f;
    }

    float mstate = -1e30f, ssum = 0.f;
    float O[8][2];
#pragma unroll
    for (int j = 0; j < 8; j++) { O[j][0] = 0.f; O[j][1] = 0.f; }

    const int tq = t >> 4, tk = t & 15;
    const int r0 = tq * 4, kk0 = tk * 8;

    for (int ch = 0; ch < NCH_; ch++) {
        for (int idx = t; idx < BKEY_ * 16; idx += 256) {
            const int kr = idx >> 4, seg = (idx & 15) * 4;
            const int gi = ch * BKEY_ + kr;
            int p; int val;
            if (gi < NCLS_) {
                p = clss[gi];
                val = (mask_src[p] > 0);
            } else {
                p = s0 + gi - 320;
                val = (p >= 0 && p < S_);
                if (val) val = (mask_src[p] > 0) && (glb[p] == 0);
                if (!val) p = 0;
            }
            if ((idx & 15) == 0) kvl[kr] = val;
            const float4 kv = *reinterpret_cast<const float4*>(
                k + ((size_t)p * H_ + hh) * HD_ + seg);
            Ksd[(seg + 0) * KS_ + kr] = kv.x;
            Ksd[(seg + 1) * KS_ + kr] = kv.y;
            Ksd[(seg + 2) * KS_ + kr] = kv.z;
            Ksd[(seg + 3) * KS_ + kr] = kv.w;
            *reinterpret_cast<float4*>(Vs + kr * VS_ + seg) =
                *reinterpret_cast<const float4*>(v + ((size_t)p * H_ + hh) * HD_ + seg);
        }
        __syncthreads();

        float sc[4][8];
#pragma unroll
        for (int j = 0; j < 4; j++)
#pragma unroll
            for (int i = 0; i < 8; i++) sc[j][i] = 0.f;
#pragma unroll 8
        for (int d = 0; d < 64; d++) {
            const float4 a = *reinterpret_cast<const float4*>(Qsd + d * 64 + r0);
            const float4 b0 = *reinterpret_cast<const float4*>(Ksd + d * KS_ + kk0);
            const float4 b1 = *reinterpret_cast<const float4*>(Ksd + d * KS_ + kk0 + 4);
            const float aa[4] = {a.x, a.y, a.z, a.w};
            const float bb[8] = {b0.x, b0.y, b0.z, b0.w, b1.x, b1.y, b1.z, b1.w};
#pragma unroll
            for (int j = 0; j < 4; j++)
#pragma unroll
                for (int i = 0; i < 8; i++) sc[j][i] = fmaf(aa[j], bb[i], sc[j][i]);
        }
#pragma unroll
        for (int i = 0; i < 8; i++) {
            const int gi = ch * BKEY_ + kk0 + i;
            const int kvalid = kvl[kk0 + i];
#pragma unroll
            for (int j = 0; j < 4; j++) {
                const int r = r0 + j;
                const bool ok = kvalid &&
                    (gi < NCLS_ || (r >= gi - 576 && r <= gi - 64));
                Pkq[(kk0 + i) * PS_ + r] = ok ? sc[j][i] : -1e30f;
            }
        }
        __syncthreads();

        if (t < 64) {
            float mn = mstate;
            for (int kk = 0; kk < BKEY_; kk++) mn = fmaxf(mn, Pkq[kk * PS_ + t]);
            const float scale = (mn <= -1e29f) ? 1.f : __expf(mstate - mn);
            float ls = 0.f;
            for (int kk = 0; kk < BKEY_; kk++) {
                const float sv = Pkq[kk * PS_ + t];
                const float pv = (sv <= -1e29f) ? 0.f : __expf(sv - mn);
                Pkq[kk * PS_ + t] = pv;
                ls += pv;
            }
            ssum = ssum * scale + ls;
            mstate = mn;
            ssc[t] = scale;
        }
        __syncthreads();

        {
#pragma unroll
            for (int j = 0; j < 8; j++) {
                const float scj = ssc[w * 8 + j];
                O[j][0] *= scj; O[j][1] *= scj;
            }
            for (int kk = 0; kk < BKEY_; kk++) {
                const float4 pa = *reinterpret_cast<const float4*>(Pkq + kk * PS_ + w * 8);
                const float4 pb = *reinterpret_cast<const float4*>(Pkq + kk * PS_ + w * 8 + 4);
                const float v0 = Vs[kk * VS_ + lane];
                const float v1 = Vs[kk * VS_ + lane + 32];
                O[0][0] = fmaf(pa.x, v0, O[0][0]); O[0][1] = fmaf(pa.x, v1, O[0][1]);
                O[1][0] = fmaf(pa.y, v0, O[1][0]); O[1][1] = fmaf(pa.y, v1, O[1][1]);
                O[2][0] = fmaf(pa.z, v0, O[2][0]); O[2][1] = fmaf(pa.z, v1, O[2][1]);
                O[3][0] = fmaf(pa.w, v0, O[3][0]); O[3][1] = fmaf(pa.w, v1, O[3][1]);
                O[4][0] = fmaf(pb.x, v0, O[4][0]); O[4][1] = fmaf(pb.x, v1, O[4][1]);
                O[5][0] = fmaf(pb.y, v0, O[5][0]); O[5][1] = fmaf(pb.y, v1, O[5][1]);
                O[6][0] = fmaf(pb.z, v0, O[6][0]); O[6][1] = fmaf(pb.z, v1, O[6][1]);
                O[7][0] = fmaf(pb.w, v0, O[7][0]); O[7][1] = fmaf(pb.w, v1, O[7][1]);
            }
        }
        __syncthreads();
    }

    if (t < 64) sin_[t] = 1.f / ssum;
    __syncthreads();
#pragma unroll
    for (int j = 0; j < 8; j++) {
        const int qr = w * 8 + j;
        const float inv = sin_[qr];
        float* op = out + ((size_t)(s0 + qr) * H_ + hh) * HD_;
        op[lane]      = O[j][0] * inv;
        op[lane + 32] = O[j][1] * inv;
    }
}

// ---------------- global-query full attention: one block per (c, head) ----------------
__global__ __launch_bounds__(256) void glb_attn_kernel(
    const float* __restrict__ qg, const float* __restrict__ kg, const float* __restrict__ vg,
    const int* __restrict__ clss, const int* __restrict__ mask_src,
    float* __restrict__ out)
{
    const int c = blockIdx.x;
    const int h = blockIdx.y;
    __shared__ float qs[HD_];
    __shared__ float sc[S_];
    __shared__ float red[256];
    const int tid = threadIdx.x;
    const int lane = tid & 31;
    const int w = tid >> 5;

    if (tid < HD_) qs[tid] = qg[((size_t)c * H_ + h) * HD_ + tid] * 0.125f;
    __syncthreads();

    for (int p = w; p < S_; p += 8) {
        const float* kp = kg + ((size_t)p * H_ + h) * HD_;
        float sdot = qs[lane] * kp[lane] + qs[lane + 32] * kp[lane + 32];
#pragma unroll
        for (int o = 16; o > 0; o >>= 1) sdot += __shfl_xor_sync(0xffffffffu, sdot, o);
        if (lane == 0) sc[p] = (mask_src[p] > 0) ? sdot : -1e30f;
    }
    __syncthreads();

    float m = -1e30f;
    for (int p = tid; p < S_; p += 256) m = fmaxf(m, sc[p]);
    red[tid] = m; __syncthreads();
    for (int o = 128; o > 0; o >>= 1) { if (tid < o) red[tid] = fmaxf(red[tid], red[tid + o]); __syncthreads(); }
    m = red[0];
    __syncthreads();
    float sum = 0.f;
    for (int p = tid; p < S_; p += 256) { float e = __expf(sc[p] - m); sc[p] = e; sum += e; }
    red[tid] = sum; __syncthreads();
    for (int o = 128; o > 0; o >>= 1) { if (tid < o) red[tid] += red[tid + o]; __syncthreads(); }
    float inv = 1.f / red[0];
    __syncthreads();

    int d = tid & 63, quarter = tid >> 6;
    float acc = 0.f;
    for (int p = quarter; p < S_; p += 4)
        acc += sc[p] * vg[((size_t)p * H_ + h) * HD_ + d];
    red[tid] = acc; __syncthreads();
    if (tid < 64) {
        float o = (red[tid] + red[tid + 64] + red[tid + 128] + red[tid + 192]) * inv;
        int gp = clss[c];
        out[((size_t)gp * H_ + h) * HD_ + tid] = o;
    }
}

// ---------------- driver ----------------
static void run_gemm(const float* A, const float* B, const float* bias, float* C,
                     int M, int N, int K, int act)
{
    dim3 grid(N / 128, (M + 127) / 128);
    sgemm_kernel<<<grid, 256>>>(A, B, bias, C, M, N, K, act);
}

extern "C" void kernel_launch(void* const* d_in, const int* in_sizes, int n_in,
                              void* d_out, int out_size)
{
    (void)in_sizes; (void)n_in;
    const int*   x        = (const int*)d_in[0];
    const int*   mask_src = (const int*)d_in[1];
    const int*   clss     = (const int*)d_in[2];
    const int*   segs     = (const int*)d_in[3];
    const float* word_emb = (const float*)d_in[4];
    const float* pos_emb  = (const float*)d_in[5];
    const float* type_emb = (const float*)d_in[6];
    const float* ln_e_s   = (const float*)d_in[7];
    const float* ln_e_b   = (const float*)d_in[8];
    const float* Wq  = (const float*)d_in[9];   const float* bq  = (const float*)d_in[10];
    const float* Wk  = (const float*)d_in[11];  const float* bk  = (const float*)d_in[12];
    const float* Wv  = (const float*)d_in[13];  const float* bv  = (const float*)d_in[14];
    const float* Wqg = (const float*)d_in[15];  const float* bqg = (const float*)d_in[16];
    const float* Wkg = (const float*)d_in[17];  const float* bkg = (const float*)d_in[18];
    const float* Wvg = (const float*)d_in[19];  const float* bvg = (const float*)d_in[20];
    const float* Wo  = (const float*)d_in[21];  const float* bo  = (const float*)d_in[22];
    const float* ln1_s = (const float*)d_in[23]; const float* ln1_b = (const float*)d_in[24];
    const float* Wf1 = (const float*)d_in[25];  const float* bf1 = (const float*)d_in[26];
    const float* Wf2 = (const float*)d_in[27];  const float* bf2 = (const float*)d_in[28];
    const float* ln2_s = (const float*)d_in[29]; const float* ln2_b = (const float*)d_in[30];

    float *h, *q, *k, *v, *kg, *vg, *outb, *tmp, *ff, *hg, *qg;
    int* glb;
    cudaGetSymbolAddress((void**)&h,    g_h);
    cudaGetSymbolAddress((void**)&q,    g_q);
    cudaGetSymbolAddress((void**)&k,    g_k);
    cudaGetSymbolAddress((void**)&v,    g_v);
    cudaGetSymbolAddress((void**)&kg,   g_kg);
    cudaGetSymbolAddress((void**)&vg,   g_vg);
    cudaGetSymbolAddress((void**)&outb, g_out);
    cudaGetSymbolAddress((void**)&tmp,  g_tmp);
    cudaGetSymbolAddress((void**)&ff,   g_ff);
    cudaGetSymbolAddress((void**)&hg,   g_hg);
    cudaGetSymbolAddress((void**)&qg,   g_qg);
    cudaGetSymbolAddress((void**)&glb,  g_glb);

    cudaFuncSetAttribute(band_attn_tiled_kernel,
                         cudaFuncAttributeMaxDynamicSharedMemorySize, BAND_SMEM);

    // embedding + LN
    embed_ln_kernel<<<S_, 256>>>(x, segs, word_emb, pos_emb, type_emb, ln_e_s, ln_e_b, h);

    // global flags
    zero_flags_kernel<<<(S_ + 255) / 256, 256>>>(glb);
    set_flags_kernel<<<1, 64>>>(clss, glb);

    const size_t DD = (size_t)D_ * D_;
    for (int l = 0; l < LAYERS_; l++) {
        // Q K V projections
        run_gemm(h, Wq + l * DD, bq + l * D_, q, S_, D_, D_, 0);
        run_gemm(h, Wk + l * DD, bk + l * D_, k, S_, D_, D_, 0);
        run_gemm(h, Wv + l * DD, bv + l * D_, v, S_, D_, D_, 0);

        // tiled band + global-key attention (writes all rows of outb)
        band_attn_tiled_kernel<<<dim3(S_ / 64, H_), 256, BAND_SMEM>>>(
            q, k, v, clss, mask_src, glb, outb);

        // global-query path
        gather_rows_kernel<<<NCLS_, 256>>>(h, clss, hg);
        run_gemm(hg, Wqg + l * DD, bqg + l * D_, qg, NCLS_, D_, D_, 0);
        run_gemm(h, Wkg + l * DD, bkg + l * D_, kg, S_, D_, D_, 0);
        run_gemm(h, Wvg + l * DD, bvg + l * D_, vg, S_, D_, D_, 0);
        glb_attn_kernel<<<dim3(NCLS_, H_), 256>>>(qg, kg, vg, clss, mask_src, outb);

        // output projection + residual LN
        run_gemm(outb, Wo + l * DD, bo + l * D_, tmp, S_, D_, D_, 0);
        add_ln_kernel<<<S_, 256>>>(h, tmp, ln1_s + l * D_, ln1_b + l * D_);

        // feed-forward
        run_gemm(h,  Wf1 + (size_t)l * D_ * FF_, bf1 + l * FF_, ff,  S_, FF_, D_, 1);
        run_gemm(ff, Wf2 + (size_t)l * D_ * FF_, bf2 + l * D_,  tmp, S_, D_, FF_, 0);
        add_ln_kernel<<<S_, 256>>>(h, tmp, ln2_s + l * D_, ln2_b + l * D_);
    }

    cudaMemcpyAsync(d_out, h, (size_t)out_size * sizeof(float), cudaMemcpyDeviceToDevice);
}